// round 2
// baseline (speedup 1.0000x reference)
#include <cuda_runtime.h>
#include <math.h>

#define NN   50000
#define E2C  400000
#define EE   800000
#define DINC 512
#define DHC  128
#define CCH  8
#define KITER 5

// ---------------- scratch (device globals; no allocation allowed) ----------
__device__ __align__(16) float g_logb0[NN * CCH];
__device__ __align__(16) float g_logb [NN * CCH];
__device__ __align__(16) float g_agg  [NN * CCH];
__device__ __align__(16) float g_msg0 [EE * CCH];
__device__ __align__(16) float g_msg1 [EE * CCH];
__device__ __align__(16) float g_logH [CCH * CCH];

// ---------------- MLP: log_b0 = log_softmax(relu(x@W1+b1)@W2+b2) -----------
// Block: 256 threads, computes 64 rows x 128 cols of h, then 2nd layer.
#define BM 64
#define BK 32

__global__ void mlp_kernel(const float* __restrict__ x,
                           const float* __restrict__ W1,
                           const float* __restrict__ b1,
                           const float* __restrict__ W2,
                           const float* __restrict__ b2) {
    // shared buffer union: phase 1 uses As (transposed, padded) + Bs,
    // phase 2 reuses it as Hs[64][129].
    __shared__ float buf[64 * 129];   // 8256 floats = 33 KB
    float* As = buf;                  // As[k][r] : k*65 + r   (32 x 65)
    float* Bs = buf + BK * 65;        // Bs[k][c] : k*128 + c  (32 x 128), 16B aligned
    float* Hs = buf;                  // Hs[r][k] : r*129 + k  (64 x 129)

    const int tid = threadIdx.x;
    const int block_row = blockIdx.x * BM;
    const int tcol = (tid & 31) * 4;   // 4 cols
    const int trow = (tid >> 5) * 8;   // 8 rows

    float acc[8][4];
#pragma unroll
    for (int i = 0; i < 8; i++)
#pragma unroll
        for (int j = 0; j < 4; j++) acc[i][j] = 0.f;

    for (int k0 = 0; k0 < DINC; k0 += BK) {
        // load A tile (64x32) transposed into As[k][r]
#pragma unroll
        for (int i = 0; i < 8; i++) {
            int idx = tid + i * 256;          // 0..2047
            int r = idx >> 5;                 // / BK
            int c = idx & 31;                 // % BK
            int gr = block_row + r;
            float v = (gr < NN) ? x[gr * DINC + k0 + c] : 0.f;
            As[c * 65 + r] = v;
        }
        // load B tile (32x128)
#pragma unroll
        for (int i = 0; i < 16; i++) {
            int idx = tid + i * 256;          // 0..4095
            int r = idx >> 7;                 // / 128
            int c = idx & 127;                // % 128
            Bs[r * 128 + c] = W1[(k0 + r) * DHC + c];
        }
        __syncthreads();

#pragma unroll
        for (int k = 0; k < BK; k++) {
            float a[8];
#pragma unroll
            for (int i = 0; i < 8; i++) a[i] = As[k * 65 + trow + i];
            float4 b4 = *(const float4*)&Bs[k * 128 + tcol];
            float b[4] = {b4.x, b4.y, b4.z, b4.w};
#pragma unroll
            for (int i = 0; i < 8; i++)
#pragma unroll
                for (int j = 0; j < 4; j++)
                    acc[i][j] = fmaf(a[i], b[j], acc[i][j]);
        }
        __syncthreads();
    }

    // h = relu(acc + b1) -> Hs
#pragma unroll
    for (int j = 0; j < 4; j++) {
        float bb = b1[tcol + j];
#pragma unroll
        for (int i = 0; i < 8; i++) {
            float v = acc[i][j] + bb;
            Hs[(trow + i) * 129 + (tcol + j)] = v > 0.f ? v : 0.f;
        }
    }
    __syncthreads();

    // second layer + log_softmax: one thread per row (64 rows)
    if (tid < BM) {
        int gr = block_row + tid;
        if (gr < NN) {
            float lg[CCH];
#pragma unroll
            for (int c = 0; c < CCH; c++) lg[c] = b2[c];
            for (int k = 0; k < DHC; k++) {
                float h = Hs[tid * 129 + k];
#pragma unroll
                for (int c = 0; c < CCH; c++)
                    lg[c] = fmaf(h, W2[k * CCH + c], lg[c]);
            }
            float mx = lg[0];
#pragma unroll
            for (int c = 1; c < CCH; c++) mx = fmaxf(mx, lg[c]);
            float s = 0.f;
#pragma unroll
            for (int c = 0; c < CCH; c++) s += __expf(lg[c] - mx);
            float lse = mx + __logf(s);
#pragma unroll
            for (int c = 0; c < CCH; c++) g_logb0[gr * CCH + c] = lg[c] - lse;
        }
    }
}

// ---------------- logH = logsigmoid(param + param^T) -----------------------
__global__ void logh_kernel(const float* __restrict__ param) {
    int i = threadIdx.x;
    if (i < CCH * CCH) {
        int r = i >> 3, c = i & 7;
        float z = param[r * CCH + c] + param[c * CCH + r];
        float t = fabsf(z);
        g_logH[i] = fminf(z, 0.f) - log1pf(expf(-t));
    }
}

__global__ void zero_kernel() {
    int i = blockIdx.x * blockDim.x + threadIdx.x;
    if (i < NN * CCH) g_agg[i] = 0.f;
}

// ---------------- edge kernel: messages + scatter-add ----------------------
__global__ void edge_kernel(const int* __restrict__ srcp,
                            const int* __restrict__ dstp,
                            const float* __restrict__ wp,
                            const int* __restrict__ rvp,
                            int iter) {
    __shared__ float Hs[CCH * CCH];
    if (threadIdx.x < CCH * CCH) Hs[threadIdx.x] = g_logH[threadIdx.x];
    __syncthreads();

    int e = blockIdx.x * blockDim.x + threadIdx.x;
    if (e >= EE) return;

    const float* logb = (iter == 0) ? g_logb0 : g_logb;
    const float* prev = (iter == 0) ? nullptr : ((iter & 1) ? g_msg0 : g_msg1);
    float* cur = (iter & 1) ? g_msg1 : g_msg0;

    int s = srcp[e];
    const float4* bp = (const float4*)(logb + s * CCH);
    float4 v0 = bp[0], v1 = bp[1];
    float xj[8] = {v0.x, v0.y, v0.z, v0.w, v1.x, v1.y, v1.z, v1.w};

    if (prev) {
        int r = rvp[e];
        const float4* pp = (const float4*)(prev + r * CCH);
        float4 p0 = pp[0], p1 = pp[1];
        xj[0] -= p0.x; xj[1] -= p0.y; xj[2] -= p0.z; xj[3] -= p0.w;
        xj[4] -= p1.x; xj[5] -= p1.y; xj[6] -= p1.z; xj[7] -= p1.w;
    }

    float w = wp[e];

    float m[8];
#pragma unroll
    for (int c = 0; c < 8; c++) {
        float t[8];
        float mx = -1e30f;
#pragma unroll
        for (int cp = 0; cp < 8; cp++) {
            t[cp] = fmaf(w, Hs[cp * 8 + c], xj[cp]);
            mx = fmaxf(mx, t[cp]);
        }
        float ssum = 0.f;
#pragma unroll
        for (int cp = 0; cp < 8; cp++) ssum += __expf(t[cp] - mx);
        m[c] = mx + __logf(ssum);
    }
    // normalize message over c
    float mx2 = m[0];
#pragma unroll
    for (int c = 1; c < 8; c++) mx2 = fmaxf(mx2, m[c]);
    float s2 = 0.f;
#pragma unroll
    for (int c = 0; c < 8; c++) s2 += __expf(m[c] - mx2);
    float lse = mx2 + __logf(s2);
#pragma unroll
    for (int c = 0; c < 8; c++) m[c] -= lse;

    float4* cp4 = (float4*)(cur + e * CCH);
    cp4[0] = make_float4(m[0], m[1], m[2], m[3]);
    cp4[1] = make_float4(m[4], m[5], m[6], m[7]);

    int d = dstp[e];
    float* ag = g_agg + d * CCH;
#pragma unroll
    for (int c = 0; c < 8; c++) atomicAdd(ag + c, m[c]);
}

// ---------------- node kernel: normalize beliefs, reset agg ----------------
__global__ void node_kernel(float* __restrict__ outp, int final_iter) {
    int i = blockIdx.x * blockDim.x + threadIdx.x;
    if (i >= NN) return;

    const float4* b0 = (const float4*)(g_logb0 + i * CCH);
    float4* ag = (float4*)(g_agg + i * CCH);
    float4 a0 = b0[0], a1 = b0[1];
    float4 g0 = ag[0], g1 = ag[1];

    float v[8] = {a0.x + g0.x, a0.y + g0.y, a0.z + g0.z, a0.w + g0.w,
                  a1.x + g1.x, a1.y + g1.y, a1.z + g1.z, a1.w + g1.w};

    float mx = v[0];
#pragma unroll
    for (int c = 1; c < 8; c++) mx = fmaxf(mx, v[c]);
    float s = 0.f;
#pragma unroll
    for (int c = 0; c < 8; c++) s += __expf(v[c] - mx);
    float lse = mx + __logf(s);

    float* o = final_iter ? (outp + i * CCH) : (g_logb + i * CCH);
    float4* o4 = (float4*)o;
    o4[0] = make_float4(v[0] - lse, v[1] - lse, v[2] - lse, v[3] - lse);
    o4[1] = make_float4(v[4] - lse, v[5] - lse, v[6] - lse, v[7] - lse);

    // reset agg for next iteration
    float4 z = make_float4(0.f, 0.f, 0.f, 0.f);
    ag[0] = z; ag[1] = z;
}

// ---------------- launch ---------------------------------------------------
extern "C" void kernel_launch(void* const* d_in, const int* in_sizes, int n_in,
                              void* d_out, int out_size) {
    const float* x     = (const float*)d_in[0];
    const int*   ei    = (const int*)  d_in[1];
    const float* ew    = (const float*)d_in[2];
    const int*   rv    = (const int*)  d_in[3];
    const float* W1    = (const float*)d_in[4];
    const float* b1    = (const float*)d_in[5];
    const float* W2    = (const float*)d_in[6];
    const float* b2    = (const float*)d_in[7];
    const float* param = (const float*)d_in[8];
    const int* srcp = ei;
    const int* dstp = ei + EE;
    float* outp = (float*)d_out;

    mlp_kernel<<<(NN + BM - 1) / BM, 256>>>(x, W1, b1, W2, b2);
    logh_kernel<<<1, 64>>>(param);
    zero_kernel<<<(NN * CCH + 255) / 256, 256>>>();

    for (int it = 0; it < KITER; it++) {
        edge_kernel<<<(EE + 255) / 256, 256>>>(srcp, dstp, ew, rv, it);
        node_kernel<<<(NN + 255) / 256, 256>>>(outp, it == KITER - 1);
    }
}

// round 6
// speedup vs baseline: 1.4690x; 1.4690x over previous
#include <cuda_runtime.h>
#include <math.h>

#define NN   50000
#define E2C  400000
#define EE   800000
#define DINC 512
#define DHC  128
#define CCH  8
#define KITER 5

#define LOG2E 1.4426950408889634f
#define LN2   0.6931471805599453f

// ---------------- scratch (device globals; no allocation allowed) ----------
__device__ __align__(16) float g_logb0[NN * CCH];
__device__ __align__(16) float g_logb [NN * CCH];
__device__ __align__(16) float g_agg  [NN * CCH];
__device__ __align__(16) float g_msg0 [EE * CCH];
__device__ __align__(16) float g_msg1 [EE * CCH];
__device__ __align__(16) float g_logH [CCH * CCH];

// ---------------- fast math helpers ----------------------------------------
__device__ __forceinline__ float fex2(float x) {
    float r; asm("ex2.approx.ftz.f32 %0, %1;" : "=f"(r) : "f"(x)); return r;
}
__device__ __forceinline__ float flg2(float x) {
    float r; asm("lg2.approx.ftz.f32 %0, %1;" : "=f"(r) : "f"(x)); return r;
}
__device__ __forceinline__ unsigned long long pack2(float lo, float hi) {
    unsigned long long r;
    asm("mov.b64 %0, {%1, %2};" : "=l"(r) : "f"(lo), "f"(hi)); return r;
}
__device__ __forceinline__ void unpack2(float& lo, float& hi, unsigned long long v) {
    asm("mov.b64 {%0, %1}, %2;" : "=f"(lo), "=f"(hi) : "l"(v));
}
__device__ __forceinline__ void ffma2(unsigned long long& d,
                                      unsigned long long a, unsigned long long b) {
    asm("fma.rn.f32x2 %0, %1, %2, %0;" : "+l"(d) : "l"(a), "l"(b));
}
__device__ __forceinline__ void redv4(float* p, float a, float b, float c, float d) {
    asm volatile("red.global.add.v4.f32 [%0], {%1, %2, %3, %4};"
                 :: "l"(p), "f"(a), "f"(b), "f"(c), "f"(d) : "memory");
}

// ---------------- MLP: log_b0 = log_softmax(relu(x@W1+b1)@W2+b2) -----------
#define BM 64
#define BK 32

__global__ void mlp_kernel(const float* __restrict__ x,
                           const float* __restrict__ W1,
                           const float* __restrict__ b1,
                           const float* __restrict__ W2,
                           const float* __restrict__ b2) {
    // phase 1: As (32 x 66 transposed) + Bs (32 x 128). phase 2: Hs (64 x 129).
    __shared__ __align__(16) float buf[64 * 129];   // 8256 floats
    __shared__ __align__(16) float W2s[DHC * CCH];  // 1024 floats
    float* As = buf;                   // As[k][r] : k*66 + r
    float* Bs = buf + BK * 66;         // Bs[k][c] : k*128 + c (16B aligned: 2112*4)
    float* Hs = buf;                   // Hs[r][k] : r*129 + k

    const int tid = threadIdx.x;
    const int block_row = blockIdx.x * BM;
    const int tcol = (tid & 31) * 4;   // 4 cols of h
    const int trow = (tid >> 5) * 8;   // 8 rows of h

    // stage W2 into shared (needed in phase 2)
#pragma unroll
    for (int i = 0; i < 4; i++) W2s[tid + i * 256] = W2[tid + i * 256];

    unsigned long long acc2[4][4];     // [row-pair][col] = {acc[2p][j], acc[2p+1][j]}
#pragma unroll
    for (int p = 0; p < 4; p++)
#pragma unroll
        for (int j = 0; j < 4; j++) acc2[p][j] = 0ULL;

    for (int k0 = 0; k0 < DINC; k0 += BK) {
        // load A tile (64x32) transposed into As[k][r]
#pragma unroll
        for (int i = 0; i < 8; i++) {
            int idx = tid + i * 256;
            int r = idx >> 5;
            int c = idx & 31;
            int gr = block_row + r;
            float v = (gr < NN) ? x[gr * DINC + k0 + c] : 0.f;
            As[c * 66 + r] = v;
        }
        // load B tile (32x128)
#pragma unroll
        for (int i = 0; i < 16; i++) {
            int idx = tid + i * 256;
            int r = idx >> 7;
            int c = idx & 127;
            Bs[r * 128 + c] = W1[(k0 + r) * DHC + c];
        }
        __syncthreads();

#pragma unroll
        for (int k = 0; k < BK; k++) {
            unsigned long long a2[4];
#pragma unroll
            for (int p = 0; p < 4; p++)
                a2[p] = *(const unsigned long long*)&As[k * 66 + trow + 2 * p];
            float4 b4 = *(const float4*)&Bs[k * 128 + tcol];
            unsigned long long b2v[4] = {pack2(b4.x, b4.x), pack2(b4.y, b4.y),
                                         pack2(b4.z, b4.z), pack2(b4.w, b4.w)};
#pragma unroll
            for (int p = 0; p < 4; p++)
#pragma unroll
                for (int j = 0; j < 4; j++)
                    ffma2(acc2[p][j], a2[p], b2v[j]);
        }
        __syncthreads();
    }

    // h = relu(acc + b1) -> Hs
#pragma unroll
    for (int j = 0; j < 4; j++) {
        float bb = b1[tcol + j];
#pragma unroll
        for (int p = 0; p < 4; p++) {
            float lo, hi;
            unpack2(lo, hi, acc2[p][j]);
            lo += bb; hi += bb;
            Hs[(trow + 2 * p)     * 129 + (tcol + j)] = lo > 0.f ? lo : 0.f;
            Hs[(trow + 2 * p + 1) * 129 + (tcol + j)] = hi > 0.f ? hi : 0.f;
        }
    }
    __syncthreads();

    // second layer + log_softmax: 2 threads per row, 4 channels each
    if (tid < 2 * BM) {
        int row = tid >> 1;
        int ch0 = (tid & 1) * 4;
        int gr = block_row + row;
        if (gr < NN) {
            float lg[4] = {b2[ch0], b2[ch0 + 1], b2[ch0 + 2], b2[ch0 + 3]};
            for (int k = 0; k < DHC; k++) {
                float h = Hs[row * 129 + k];
                const float4 w4 = *(const float4*)&W2s[k * CCH + ch0];
                lg[0] = fmaf(h, w4.x, lg[0]);
                lg[1] = fmaf(h, w4.y, lg[1]);
                lg[2] = fmaf(h, w4.z, lg[2]);
                lg[3] = fmaf(h, w4.w, lg[3]);
            }
            float mx = fmaxf(fmaxf(lg[0], lg[1]), fmaxf(lg[2], lg[3]));
            mx = fmaxf(mx, __shfl_xor_sync(0xFFFFFFFF, mx, 1));
            float s = 0.f;
#pragma unroll
            for (int c = 0; c < 4; c++) s += fex2((lg[c] - mx) * LOG2E);
            s += __shfl_xor_sync(0xFFFFFFFF, s, 1);
            float lse = mx + flg2(s) * LN2;
#pragma unroll
            for (int c = 0; c < 4; c++) g_logb0[gr * CCH + ch0 + c] = lg[c] - lse;
        }
    }
}

// ---------------- logH = logsigmoid(param + param^T) -----------------------
__global__ void logh_kernel(const float* __restrict__ param) {
    int i = threadIdx.x;
    if (i < CCH * CCH) {
        int r = i >> 3, c = i & 7;
        float z = param[r * CCH + c] + param[c * CCH + r];
        float t = fabsf(z);
        g_logH[i] = fminf(z, 0.f) - log1pf(expf(-t));
    }
}

__global__ void zero_kernel() {
    int i = blockIdx.x * blockDim.x + threadIdx.x;
    if (i < NN * CCH) g_agg[i] = 0.f;
}

// ---------------- edge kernel: one thread per UNDIRECTED edge --------------
// Both directions share w and the symmetric H, so the 8x8 coupling matrix
// G = exp(w*logH) is computed once and used for both messages. The tropical
// matvec runs in linear domain: S[c] = sum_cp E[cp] * G[cp][c].
__global__ void edge_kernel(const int* __restrict__ srcp,
                            const int* __restrict__ dstp,
                            const float* __restrict__ wp,
                            int iter) {
    __shared__ float H2s[CCH * CCH];   // logH * log2(e)
    if (threadIdx.x < CCH * CCH) H2s[threadIdx.x] = g_logH[threadIdx.x] * LOG2E;
    __syncthreads();

    int u = blockIdx.x * blockDim.x + threadIdx.x;
    if (u >= E2C) return;

    const float* logb = (iter == 0) ? g_logb0 : g_logb;
    const float* prev = (iter & 1) ? g_msg0 : g_msg1;
    float* cur = (iter & 1) ? g_msg1 : g_msg0;

    int s = srcp[u];
    int d = dstp[u];
    float w = wp[u];

    float xs[8], xd[8];
    {
        const float4* bp = (const float4*)(logb + s * CCH);
        float4 v0 = bp[0], v1 = bp[1];
        xs[0]=v0.x; xs[1]=v0.y; xs[2]=v0.z; xs[3]=v0.w;
        xs[4]=v1.x; xs[5]=v1.y; xs[6]=v1.z; xs[7]=v1.w;
        const float4* bq = (const float4*)(logb + d * CCH);
        float4 u0 = bq[0], u1 = bq[1];
        xd[0]=u0.x; xd[1]=u0.y; xd[2]=u0.z; xd[3]=u0.w;
        xd[4]=u1.x; xd[5]=u1.y; xd[6]=u1.z; xd[7]=u1.w;
    }
    if (iter != 0) {
        // reverse of edge u is u+E2C, reverse of u+E2C is u (structural)
        const float4* pf = (const float4*)(prev + (size_t)(u + E2C) * CCH);
        float4 p0 = pf[0], p1 = pf[1];
        xs[0]-=p0.x; xs[1]-=p0.y; xs[2]-=p0.z; xs[3]-=p0.w;
        xs[4]-=p1.x; xs[5]-=p1.y; xs[6]-=p1.z; xs[7]-=p1.w;
        const float4* pb = (const float4*)(prev + (size_t)u * CCH);
        float4 q0 = pb[0], q1 = pb[1];
        xd[0]-=q0.x; xd[1]-=q0.y; xd[2]-=q0.z; xd[3]-=q0.w;
        xd[4]-=q1.x; xd[5]-=q1.y; xd[6]-=q1.z; xd[7]-=q1.w;
    }

    float mxs = xs[0], mxd = xd[0];
#pragma unroll
    for (int c = 1; c < 8; c++) { mxs = fmaxf(mxs, xs[c]); mxd = fmaxf(mxd, xd[c]); }

    float Ef[8], Eb[8];
#pragma unroll
    for (int c = 0; c < 8; c++) {
        Ef[c] = fex2((xs[c] - mxs) * LOG2E);
        Eb[c] = fex2((xd[c] - mxd) * LOG2E);
    }

    float Sf[8] = {0,0,0,0,0,0,0,0};
    float Sb[8] = {0,0,0,0,0,0,0,0};
#pragma unroll
    for (int cp = 0; cp < 8; cp++) {
#pragma unroll
        for (int c = 0; c < 8; c++) {
            float g = fex2(w * H2s[cp * 8 + c]);   // shared by both directions
            Sf[c] = fmaf(Ef[cp], g, Sf[c]);
            Sb[c] = fmaf(Eb[cp], g, Sb[c]);
        }
    }

    float totf = 0.f, totb = 0.f;
#pragma unroll
    for (int c = 0; c < 8; c++) { totf += Sf[c]; totb += Sb[c]; }
    float ltf = flg2(totf), ltb = flg2(totb);

    float mf[8], mb[8];
#pragma unroll
    for (int c = 0; c < 8; c++) {
        mf[c] = (flg2(Sf[c]) - ltf) * LN2;   // normalized fwd message (natural log)
        mb[c] = (flg2(Sb[c]) - ltb) * LN2;   // normalized bwd message
    }

    float4* cf = (float4*)(cur + (size_t)u * CCH);
    cf[0] = make_float4(mf[0], mf[1], mf[2], mf[3]);
    cf[1] = make_float4(mf[4], mf[5], mf[6], mf[7]);
    float4* cb = (float4*)(cur + (size_t)(u + E2C) * CCH);
    cb[0] = make_float4(mb[0], mb[1], mb[2], mb[3]);
    cb[1] = make_float4(mb[4], mb[5], mb[6], mb[7]);

    float* agd = g_agg + (size_t)d * CCH;   // fwd message aggregates at dst
    redv4(agd,     mf[0], mf[1], mf[2], mf[3]);
    redv4(agd + 4, mf[4], mf[5], mf[6], mf[7]);
    float* ags = g_agg + (size_t)s * CCH;   // bwd message aggregates at src
    redv4(ags,     mb[0], mb[1], mb[2], mb[3]);
    redv4(ags + 4, mb[4], mb[5], mb[6], mb[7]);
}

// ---------------- node kernel: normalize beliefs, reset agg ----------------
__global__ void node_kernel(float* __restrict__ outp, int final_iter) {
    int i = blockIdx.x * blockDim.x + threadIdx.x;
    if (i >= NN) return;

    const float4* b0 = (const float4*)(g_logb0 + (size_t)i * CCH);
    float4* ag = (float4*)(g_agg + (size_t)i * CCH);
    float4 a0 = b0[0], a1 = b0[1];
    float4 g0 = ag[0], g1 = ag[1];

    float v[8] = {a0.x + g0.x, a0.y + g0.y, a0.z + g0.z, a0.w + g0.w,
                  a1.x + g1.x, a1.y + g1.y, a1.z + g1.z, a1.w + g1.w};

    float mx = v[0];
#pragma unroll
    for (int c = 1; c < 8; c++) mx = fmaxf(mx, v[c]);
    float sacc = 0.f;
#pragma unroll
    for (int c = 0; c < 8; c++) sacc += fex2((v[c] - mx) * LOG2E);
    float lse = mx + flg2(sacc) * LN2;

    float* o = final_iter ? (outp + (size_t)i * CCH) : (g_logb + (size_t)i * CCH);
    float4* o4 = (float4*)o;
    o4[0] = make_float4(v[0] - lse, v[1] - lse, v[2] - lse, v[3] - lse);
    o4[1] = make_float4(v[4] - lse, v[5] - lse, v[6] - lse, v[7] - lse);

    float4 z = make_float4(0.f, 0.f, 0.f, 0.f);
    ag[0] = z; ag[1] = z;
}

// ---------------- launch ---------------------------------------------------
extern "C" void kernel_launch(void* const* d_in, const int* in_sizes, int n_in,
                              void* d_out, int out_size) {
    const float* x     = (const float*)d_in[0];
    const int*   ei    = (const int*)  d_in[1];
    const float* ew    = (const float*)d_in[2];
    const float* W1    = (const float*)d_in[4];
    const float* b1    = (const float*)d_in[5];
    const float* W2    = (const float*)d_in[6];
    const float* b2    = (const float*)d_in[7];
    const float* param = (const float*)d_in[8];
    const int* srcp = ei;          // first E2C entries are the undirected srcs
    const int* dstp = ei + EE;     // dst row; first E2C entries pair with srcp
    float* outp = (float*)d_out;

    mlp_kernel<<<(NN + BM - 1) / BM, 256>>>(x, W1, b1, W2, b2);
    logh_kernel<<<1, 64>>>(param);
    zero_kernel<<<(NN * CCH + 255) / 256, 256>>>();

    for (int it = 0; it < KITER; it++) {
        edge_kernel<<<(E2C + 255) / 256, 256>>>(srcp, dstp, ew, it);
        node_kernel<<<(NN + 255) / 256, 256>>>(outp, it == KITER - 1);
    }
}

// round 8
// speedup vs baseline: 2.7107x; 1.8453x over previous
#include <cuda_runtime.h>
#include <math.h>
#include <stdint.h>

#define NN   50000
#define E2C  400000
#define EE   800000
#define DINC 512
#define DHC  128
#define CCH  8
#define KITER 5

#define LOG2E 1.4426950408889634f
#define LN2   0.6931471805599453f

// ---------------- scratch (device globals; no allocation allowed) ----------
__device__ __align__(16) float g_logb0[NN * CCH];
__device__ __align__(16) float g_logb [NN * CCH];
__device__ __align__(16) float g_agg  [NN * CCH];
__device__ __align__(16) float g_msg0 [EE * CCH];
__device__ __align__(16) float g_msg1 [EE * CCH];
__device__ __align__(16) float g_logH [CCH * CCH];

// ---------------- fast math helpers ----------------------------------------
__device__ __forceinline__ float fex2(float x) {
    float r; asm("ex2.approx.ftz.f32 %0, %1;" : "=f"(r) : "f"(x)); return r;
}
__device__ __forceinline__ float flg2(float x) {
    float r; asm("lg2.approx.ftz.f32 %0, %1;" : "=f"(r) : "f"(x)); return r;
}
__device__ __forceinline__ void redv4(float* p, float a, float b, float c, float d) {
    asm volatile("red.global.add.v4.f32 [%0], {%1, %2, %3, %4};"
                 :: "l"(p), "f"(a), "f"(b), "f"(c), "f"(d) : "memory");
}
__device__ __forceinline__ uint32_t f2tf32(float f) {
    uint32_t u; asm("cvt.rna.tf32.f32 %0, %1;" : "=r"(u) : "f"(f)); return u;
}
__device__ __forceinline__ void mma_tf32(float4& d, const uint32_t* a, const uint32_t* b) {
    asm("mma.sync.aligned.m16n8k8.row.col.f32.tf32.tf32.f32 "
        "{%0,%1,%2,%3},{%4,%5,%6,%7},{%8,%9},{%0,%1,%2,%3};"
        : "+f"(d.x), "+f"(d.y), "+f"(d.z), "+f"(d.w)
        : "r"(a[0]), "r"(a[1]), "r"(a[2]), "r"(a[3]), "r"(b[0]), "r"(b[1]));
}

// ---------------- MLP: log_b0 = log_softmax(relu(x@W1+b1)@W2+b2) -----------
// GEMM1 on tensor cores (tf32, 3xTF32 split for fp32-class accuracy).
// Block tile: 64 rows x 128 cols (full DH), K chunks of 16, 8 warps (32x32 each).
#define BM 64
#define BKC 16
#define APAD 20    // A smem row pitch:  bank = 4g+tg -> conflict-free frag loads
#define BPAD 136   // B smem row pitch:  bank = 8tg+g -> conflict-free frag loads
#define NKCH (DINC / BKC)   // 32 chunks

// smem buf offsets (in 32-bit words)
#define OFF_AHI 0
#define OFF_ALO (OFF_AHI + BM * APAD)            // 1280
#define OFF_BHI (OFF_ALO + BM * APAD)            // 2560
#define OFF_BLO (OFF_BHI + BKC * BPAD)           // 4736
#define PH1_WORDS (OFF_BLO + BKC * BPAD)         // 6912
#define HS_WORDS (BM * 129)                      // 8256
#define BUF_WORDS (HS_WORDS > PH1_WORDS ? HS_WORDS : PH1_WORDS)

__global__ void __launch_bounds__(256) mlp_kernel(const float* __restrict__ x,
                           const float* __restrict__ W1,
                           const float* __restrict__ b1,
                           const float* __restrict__ W2,
                           const float* __restrict__ b2) {
    __shared__ __align__(16) uint32_t buf[BUF_WORDS];
    __shared__ __align__(16) float W2s[DHC * CCH];
    __shared__ float b1s[DHC];

    uint32_t* Ahi = buf + OFF_AHI;
    uint32_t* Alo = buf + OFF_ALO;
    uint32_t* Bhi = buf + OFF_BHI;
    uint32_t* Blo = buf + OFF_BLO;
    float*    Hs  = (float*)buf;     // phase 2: Hs[r][k] pitch 129

    const int tid = threadIdx.x;
    const int wid = tid >> 5;
    const int lane = tid & 31;
    const int block_row = blockIdx.x * BM;

    // stage W2, b1
#pragma unroll
    for (int i = 0; i < 4; i++) W2s[tid + i * 256] = W2[tid + i * 256];
    if (tid < DHC) b1s[tid] = b1[tid];

    // global load mapping
    const int arow = tid >> 2;            // 0..63
    const int aq   = (tid & 3) * 4;       // k offset 0,4,8,12
    const int brow = tid >> 5;            // 0..7 (and +8)
    const int bcol = (tid & 31) * 4;      // 0..124
    const int gr   = block_row + arow;
    const bool avalid = (gr < NN);

    // warp tiling
    const int m0 = (wid & 1) * 32;
    const int n0 = (wid >> 1) * 32;
    const int g  = lane >> 2;             // 0..7
    const int tg = lane & 3;              // 0..3

    float4 acc[2][4];
#pragma unroll
    for (int mi = 0; mi < 2; mi++)
#pragma unroll
        for (int ni = 0; ni < 4; ni++) acc[mi][ni] = make_float4(0.f, 0.f, 0.f, 0.f);

    float4 ax = make_float4(0.f, 0.f, 0.f, 0.f), bx0, bx1;
    // preload chunk 0
    if (avalid) ax = *(const float4*)&x[(size_t)gr * DINC + aq];
    bx0 = *(const float4*)&W1[(size_t)brow * DHC + bcol];
    bx1 = *(const float4*)&W1[(size_t)(brow + 8) * DHC + bcol];

    for (int c = 0; c < NKCH; c++) {
        // convert+store staged regs (hi = tf32(v), lo = tf32(v - hi))
        {
            float av[4] = {ax.x, ax.y, ax.z, ax.w};
            uint32_t hi4[4], lo4[4];
#pragma unroll
            for (int j = 0; j < 4; j++) {
                hi4[j] = f2tf32(av[j]);
                lo4[j] = f2tf32(av[j] - __uint_as_float(hi4[j]));
            }
            *(uint4*)&Ahi[arow * APAD + aq] = *(uint4*)hi4;
            *(uint4*)&Alo[arow * APAD + aq] = *(uint4*)lo4;

            float bv0[4] = {bx0.x, bx0.y, bx0.z, bx0.w};
            float bv1[4] = {bx1.x, bx1.y, bx1.z, bx1.w};
            uint32_t h0[4], l0[4], h1[4], l1[4];
#pragma unroll
            for (int j = 0; j < 4; j++) {
                h0[j] = f2tf32(bv0[j]); l0[j] = f2tf32(bv0[j] - __uint_as_float(h0[j]));
                h1[j] = f2tf32(bv1[j]); l1[j] = f2tf32(bv1[j] - __uint_as_float(h1[j]));
            }
            *(uint4*)&Bhi[brow * BPAD + bcol] = *(uint4*)h0;
            *(uint4*)&Blo[brow * BPAD + bcol] = *(uint4*)l0;
            *(uint4*)&Bhi[(brow + 8) * BPAD + bcol] = *(uint4*)h1;
            *(uint4*)&Blo[(brow + 8) * BPAD + bcol] = *(uint4*)l1;
        }
        __syncthreads();

        // prefetch next chunk while computing this one
        if (c + 1 < NKCH) {
            int k0 = (c + 1) * BKC;
            if (avalid) ax = *(const float4*)&x[(size_t)gr * DINC + k0 + aq];
            bx0 = *(const float4*)&W1[(size_t)(k0 + brow) * DHC + bcol];
            bx1 = *(const float4*)&W1[(size_t)(k0 + brow + 8) * DHC + bcol];
        }

        // 2 k-steps of 8
#pragma unroll
        for (int ks = 0; ks < BKC; ks += 8) {
            uint32_t ah[2][4], al[2][4];
#pragma unroll
            for (int mi = 0; mi < 2; mi++) {
                int r0 = (m0 + 16 * mi + g) * APAD + ks + tg;
                int r1 = (m0 + 16 * mi + g + 8) * APAD + ks + tg;
                ah[mi][0] = Ahi[r0];     ah[mi][1] = Ahi[r1];
                ah[mi][2] = Ahi[r0 + 4]; ah[mi][3] = Ahi[r1 + 4];
                al[mi][0] = Alo[r0];     al[mi][1] = Alo[r1];
                al[mi][2] = Alo[r0 + 4]; al[mi][3] = Alo[r1 + 4];
            }
            uint32_t bh[4][2], bl[4][2];
#pragma unroll
            for (int ni = 0; ni < 4; ni++) {
                int col = n0 + 8 * ni + g;
                bh[ni][0] = Bhi[(ks + tg) * BPAD + col];
                bh[ni][1] = Bhi[(ks + tg + 4) * BPAD + col];
                bl[ni][0] = Blo[(ks + tg) * BPAD + col];
                bl[ni][1] = Blo[(ks + tg + 4) * BPAD + col];
            }
#pragma unroll
            for (int mi = 0; mi < 2; mi++)
#pragma unroll
                for (int ni = 0; ni < 4; ni++) {
                    mma_tf32(acc[mi][ni], ah[mi], bh[ni]);
                    mma_tf32(acc[mi][ni], ah[mi], bl[ni]);
                    mma_tf32(acc[mi][ni], al[mi], bh[ni]);
                }
        }
        __syncthreads();
    }

    // epilogue: h = relu(acc + b1) -> Hs (aliases phase-1 smem; synced above)
#pragma unroll
    for (int mi = 0; mi < 2; mi++) {
#pragma unroll
        for (int ni = 0; ni < 4; ni++) {
            int row = m0 + 16 * mi + g;
            int col = n0 + 8 * ni + 2 * tg;
            float bb0 = b1s[col], bb1 = b1s[col + 1];
            float v0 = acc[mi][ni].x + bb0, v1 = acc[mi][ni].y + bb1;
            float v2 = acc[mi][ni].z + bb0, v3 = acc[mi][ni].w + bb1;
            Hs[row * 129 + col]           = v0 > 0.f ? v0 : 0.f;
            Hs[row * 129 + col + 1]       = v1 > 0.f ? v1 : 0.f;
            Hs[(row + 8) * 129 + col]     = v2 > 0.f ? v2 : 0.f;
            Hs[(row + 8) * 129 + col + 1] = v3 > 0.f ? v3 : 0.f;
        }
    }
    __syncthreads();

    // second layer + log_softmax: 2 threads per row, 4 channels each
    if (tid < 2 * BM) {
        int row = tid >> 1;
        int ch0 = (tid & 1) * 4;
        int grr = block_row + row;
        if (grr < NN) {
            float lg[4] = {b2[ch0], b2[ch0 + 1], b2[ch0 + 2], b2[ch0 + 3]};
            for (int k = 0; k < DHC; k++) {
                float h = Hs[row * 129 + k];
                const float4 w4 = *(const float4*)&W2s[k * CCH + ch0];
                lg[0] = fmaf(h, w4.x, lg[0]);
                lg[1] = fmaf(h, w4.y, lg[1]);
                lg[2] = fmaf(h, w4.z, lg[2]);
                lg[3] = fmaf(h, w4.w, lg[3]);
            }
            float mx = fmaxf(fmaxf(lg[0], lg[1]), fmaxf(lg[2], lg[3]));
            mx = fmaxf(mx, __shfl_xor_sync(0xFFFFFFFF, mx, 1));
            float s = 0.f;
#pragma unroll
            for (int cc = 0; cc < 4; cc++) s += fex2((lg[cc] - mx) * LOG2E);
            s += __shfl_xor_sync(0xFFFFFFFF, s, 1);
            float lse = mx + flg2(s) * LN2;
#pragma unroll
            for (int cc = 0; cc < 4; cc++) g_logb0[grr * CCH + ch0 + cc] = lg[cc] - lse;
        }
    }
}

// ---------------- logH = logsigmoid(param + param^T) -----------------------
__global__ void logh_kernel(const float* __restrict__ param) {
    int i = threadIdx.x;
    if (i < CCH * CCH) {
        int r = i >> 3, c = i & 7;
        float z = param[r * CCH + c] + param[c * CCH + r];
        float t = fabsf(z);
        g_logH[i] = fminf(z, 0.f) - log1pf(expf(-t));
    }
}

__global__ void zero_kernel() {
    int i = blockIdx.x * blockDim.x + threadIdx.x;
    if (i < NN * CCH) g_agg[i] = 0.f;
}

// ---------------- edge kernel: one thread per UNDIRECTED edge --------------
__global__ void edge_kernel(const int* __restrict__ srcp,
                            const int* __restrict__ dstp,
                            const float* __restrict__ wp,
                            int iter) {
    __shared__ float H2s[CCH * CCH];   // logH * log2(e)
    if (threadIdx.x < CCH * CCH) H2s[threadIdx.x] = g_logH[threadIdx.x] * LOG2E;
    __syncthreads();

    int u = blockIdx.x * blockDim.x + threadIdx.x;
    if (u >= E2C) return;

    const float* logb = (iter == 0) ? g_logb0 : g_logb;
    const float* prev = (iter & 1) ? g_msg0 : g_msg1;
    float* cur = (iter & 1) ? g_msg1 : g_msg0;

    int s = srcp[u];
    int d = dstp[u];
    float w = wp[u];

    float xs[8], xd[8];
    {
        const float4* bp = (const float4*)(logb + s * CCH);
        float4 v0 = bp[0], v1 = bp[1];
        xs[0]=v0.x; xs[1]=v0.y; xs[2]=v0.z; xs[3]=v0.w;
        xs[4]=v1.x; xs[5]=v1.y; xs[6]=v1.z; xs[7]=v1.w;
        const float4* bq = (const float4*)(logb + d * CCH);
        float4 u0 = bq[0], u1 = bq[1];
        xd[0]=u0.x; xd[1]=u0.y; xd[2]=u0.z; xd[3]=u0.w;
        xd[4]=u1.x; xd[5]=u1.y; xd[6]=u1.z; xd[7]=u1.w;
    }
    if (iter != 0) {
        const float4* pf = (const float4*)(prev + (size_t)(u + E2C) * CCH);
        float4 p0 = pf[0], p1 = pf[1];
        xs[0]-=p0.x; xs[1]-=p0.y; xs[2]-=p0.z; xs[3]-=p0.w;
        xs[4]-=p1.x; xs[5]-=p1.y; xs[6]-=p1.z; xs[7]-=p1.w;
        const float4* pb = (const float4*)(prev + (size_t)u * CCH);
        float4 q0 = pb[0], q1 = pb[1];
        xd[0]-=q0.x; xd[1]-=q0.y; xd[2]-=q0.z; xd[3]-=q0.w;
        xd[4]-=q1.x; xd[5]-=q1.y; xd[6]-=q1.z; xd[7]-=q1.w;
    }

    float mxs = xs[0], mxd = xd[0];
#pragma unroll
    for (int c = 1; c < 8; c++) { mxs = fmaxf(mxs, xs[c]); mxd = fmaxf(mxd, xd[c]); }

    float Ef[8], Eb[8];
#pragma unroll
    for (int c = 0; c < 8; c++) {
        Ef[c] = fex2((xs[c] - mxs) * LOG2E);
        Eb[c] = fex2((xd[c] - mxd) * LOG2E);
    }

    float Sf[8] = {0,0,0,0,0,0,0,0};
    float Sb[8] = {0,0,0,0,0,0,0,0};
#pragma unroll
    for (int cp = 0; cp < 8; cp++) {
#pragma unroll
        for (int c = 0; c < 8; c++) {
            float gg = fex2(w * H2s[cp * 8 + c]);
            Sf[c] = fmaf(Ef[cp], gg, Sf[c]);
            Sb[c] = fmaf(Eb[cp], gg, Sb[c]);
        }
    }

    float totf = 0.f, totb = 0.f;
#pragma unroll
    for (int c = 0; c < 8; c++) { totf += Sf[c]; totb += Sb[c]; }
    float ltf = flg2(totf), ltb = flg2(totb);

    float mf[8], mb[8];
#pragma unroll
    for (int c = 0; c < 8; c++) {
        mf[c] = (flg2(Sf[c]) - ltf) * LN2;
        mb[c] = (flg2(Sb[c]) - ltb) * LN2;
    }

    float4* cf = (float4*)(cur + (size_t)u * CCH);
    cf[0] = make_float4(mf[0], mf[1], mf[2], mf[3]);
    cf[1] = make_float4(mf[4], mf[5], mf[6], mf[7]);
    float4* cb = (float4*)(cur + (size_t)(u + E2C) * CCH);
    cb[0] = make_float4(mb[0], mb[1], mb[2], mb[3]);
    cb[1] = make_float4(mb[4], mb[5], mb[6], mb[7]);

    float* agd = g_agg + (size_t)d * CCH;
    redv4(agd,     mf[0], mf[1], mf[2], mf[3]);
    redv4(agd + 4, mf[4], mf[5], mf[6], mf[7]);
    float* ags = g_agg + (size_t)s * CCH;
    redv4(ags,     mb[0], mb[1], mb[2], mb[3]);
    redv4(ags + 4, mb[4], mb[5], mb[6], mb[7]);
}

// ---------------- node kernel: normalize beliefs, reset agg ----------------
__global__ void node_kernel(float* __restrict__ outp, int final_iter) {
    int i = blockIdx.x * blockDim.x + threadIdx.x;
    if (i >= NN) return;

    const float4* b0 = (const float4*)(g_logb0 + (size_t)i * CCH);
    float4* ag = (float4*)(g_agg + (size_t)i * CCH);
    float4 a0 = b0[0], a1 = b0[1];
    float4 g0 = ag[0], g1 = ag[1];

    float v[8] = {a0.x + g0.x, a0.y + g0.y, a0.z + g0.z, a0.w + g0.w,
                  a1.x + g1.x, a1.y + g1.y, a1.z + g1.z, a1.w + g1.w};

    float mx = v[0];
#pragma unroll
    for (int c = 1; c < 8; c++) mx = fmaxf(mx, v[c]);
    float sacc = 0.f;
#pragma unroll
    for (int c = 0; c < 8; c++) sacc += fex2((v[c] - mx) * LOG2E);
    float lse = mx + flg2(sacc) * LN2;

    float* o = final_iter ? (outp + (size_t)i * CCH) : (g_logb + (size_t)i * CCH);
    float4* o4 = (float4*)o;
    o4[0] = make_float4(v[0] - lse, v[1] - lse, v[2] - lse, v[3] - lse);
    o4[1] = make_float4(v[4] - lse, v[5] - lse, v[6] - lse, v[7] - lse);

    float4 z = make_float4(0.f, 0.f, 0.f, 0.f);
    ag[0] = z; ag[1] = z;
}

// ---------------- launch ---------------------------------------------------
extern "C" void kernel_launch(void* const* d_in, const int* in_sizes, int n_in,
                              void* d_out, int out_size) {
    const float* x     = (const float*)d_in[0];
    const int*   ei    = (const int*)  d_in[1];
    const float* ew    = (const float*)d_in[2];
    const float* W1    = (const float*)d_in[4];
    const float* b1    = (const float*)d_in[5];
    const float* W2    = (const float*)d_in[6];
    const float* b2    = (const float*)d_in[7];
    const float* param = (const float*)d_in[8];
    const int* srcp = ei;          // first E2C entries are the undirected srcs
    const int* dstp = ei + EE;     // dst row; first E2C entries pair with srcp
    float* outp = (float*)d_out;

    mlp_kernel<<<(NN + BM - 1) / BM, 256>>>(x, W1, b1, W2, b2);
    logh_kernel<<<1, 64>>>(param);
    zero_kernel<<<(NN * CCH + 255) / 256, 256>>>();

    for (int it = 0; it < KITER; it++) {
        edge_kernel<<<(E2C + 255) / 256, 256>>>(srcp, dstp, ew, it);
        node_kernel<<<(NN + 255) / 256, 256>>>(outp, it == KITER - 1);
    }
}